// round 5
// baseline (speedup 1.0000x reference)
#include <cuda_runtime.h>
#include <cuda_bf16.h>

#define B_MAX 8192
#define LCH 32   // predicted chars per sample (L)
#define MLB 32   // labels per sample (M)
#define CCL 96   // classes (C)
#define WARPS_PER_BLOCK 8
#define FULLMASK 0xffffffffu

// Per-sample results (scratch; __device__ globals are allowed, allocs are not)
__device__ float g_loss[B_MAX];
__device__ int   g_flag[B_MAX];

struct WarpScratch {
    unsigned char D[33 * 34];   // DP table, row stride 34 (1122 B)
    unsigned char pad0[2];
    int   pred[LCH];            // argmax per row
    int   tgt[MLB];             // labels
    float base[LCH];            // rowmax + log(sum exp) per row
    int2  trace[LCH];           // (xi, label) for diagonal steps
    int   cnt;
    int   pad1[3];
};

__global__ void edit_loss_kernel(const float* __restrict__ x,
                                 const int* __restrict__ y, int B) {
    __shared__ WarpScratch ws[WARPS_PER_BLOCK];
    const int warp = threadIdx.x >> 5;
    const int lane = threadIdx.x & 31;
    const int s = blockIdx.x * WARPS_PER_BLOCK + warp;
    if (s >= B) return;  // whole warp exits together (s is warp-uniform)

    WarpScratch& W = ws[warp];
    const float* xs = x + (size_t)s * (LCH * CCL);

    // Load targets (one per lane)
    const int myTgt = y[s * MLB + lane];
    W.tgt[lane] = myTgt;

    // ---- Phase A: per-row argmax + logsumexp (warp handles one row at a time)
    for (int r = 0; r < LCH; ++r) {
        const float* row = xs + r * CCL;
        float f0 = row[lane];
        float f1 = row[lane + 32];
        float f2 = row[lane + 64];
        // thread-local argmax, lowest index wins ties
        float v = f0; int id = lane;
        if (f1 > v) { v = f1; id = lane + 32; }
        if (f2 > v) { v = f2; id = lane + 64; }
        #pragma unroll
        for (int off = 16; off; off >>= 1) {
            float ov = __shfl_xor_sync(FULLMASK, v, off);
            int   oi = __shfl_xor_sync(FULLMASK, id, off);
            if (ov > v || (ov == v && oi < id)) { v = ov; id = oi; }
        }
        // all lanes now hold rowmax v and argmax id
        float sum = __expf(f0 - v) + __expf(f1 - v) + __expf(f2 - v);
        #pragma unroll
        for (int off = 16; off; off >>= 1)
            sum += __shfl_xor_sync(FULLMASK, sum, off);
        if (lane == 0) {
            W.pred[r] = id;
            W.base[r] = v + __logf(sum);  // logZ for this row
        }
    }

    // ---- DP boundary rows/cols
    W.D[0 * 34 + lane] = (unsigned char)lane;   // D[0][j] = j
    W.D[lane * 34 + 0] = (unsigned char)lane;   // D[i][0] = i
    if (lane == 0) { W.D[0 * 34 + 32] = 32; W.D[32 * 34 + 0] = 32; }
    __syncwarp();

    // ---- Phase B: Levenshtein wavefront (lane t owns column j = t+1)
    {
        const int t = lane;
        const int j = lane + 1;
        unsigned int prev = 0u;    // my value from previous step  (= D[i-1][j])
        unsigned int diagv = 0u;   // neighbor's value from 2 steps ago (= D[i-1][j-1])
        #pragma unroll 1
        for (int d = 0; d <= LCH + MLB - 2; ++d) {          // 63 anti-diagonals
            unsigned int leftIn = __shfl_up_sync(FULLMASK, prev, 1);
            const int i = d - t + 1;
            if (i >= 1 && i <= LCH) {
                unsigned int c    = (W.pred[i - 1] != myTgt) ? 1u : 0u;
                unsigned int up   = (i == 1) ? (unsigned)j : prev;
                unsigned int left = (t == 0) ? (unsigned)i : leftIn;
                unsigned int dg   = (i == 1) ? (unsigned)(j - 1)
                                 : (t == 0) ? (unsigned)(i - 1)
                                            : diagv;
                unsigned int val = min(min(up, left) + 1u, dg + c);
                W.D[i * 34 + j] = (unsigned char)val;
                prev = val;
            }
            diagv = leftIn;
        }
    }
    __syncwarp();

    // ---- Phase C: backtrace (serial, lane 0). Records diagonal moves only.
    if (lane == 0) {
        int i = LCH, jj = MLB, cnt = 0;
        while (i > 0 && jj > 0) {   // once i==0 or j==0, no more diag moves possible
            const int dij = (int)W.D[i * 34 + jj];
            const int c = (W.pred[i - 1] != W.tgt[jj - 1]) ? 1 : 0;
            if ((int)W.D[(i - 1) * 34 + (jj - 1)] + c == dij) {
                W.trace[cnt] = make_int2(i - 1, W.tgt[jj - 1]);
                ++cnt; --i; --jj;
            } else if ((int)W.D[(i - 1) * 34 + jj] + 1 == dij) {
                --i;
            } else {
                --jj;
            }
        }
        W.cnt = cnt;
    }
    __syncwarp();

    // ---- Phase D: CE gather + warp reduce
    const int cnt = W.cnt;
    float ce = 0.f;
    if (lane < cnt) {
        const int2 tr = W.trace[lane];
        const float val = __ldg(&xs[tr.x * CCL + tr.y]);  // L2-hot: just streamed
        ce = W.base[tr.x] - val;                          // -log_softmax at (row, label)
    }
    #pragma unroll
    for (int off = 16; off; off >>= 1)
        ce += __shfl_xor_sync(FULLMASK, ce, off);
    if (lane == 0) {
        g_loss[s] = (cnt > 0) ? (ce / (float)cnt) : 0.f;
        g_flag[s] = (cnt > 0) ? 1 : 0;
    }
}

// Deterministic final reduction: fixed-order strided accumulation + smem tree.
__global__ void edit_loss_reduce_kernel(float* __restrict__ out, int B) {
    __shared__ double ssum[256];
    __shared__ int    scnt[256];
    const int tid = threadIdx.x;
    double sum = 0.0; int cnt = 0;
    for (int i = tid; i < B; i += 256) {
        sum += (double)g_loss[i];
        cnt += g_flag[i];
    }
    ssum[tid] = sum; scnt[tid] = cnt;
    __syncthreads();
    #pragma unroll
    for (int s = 128; s; s >>= 1) {
        if (tid < s) { ssum[tid] += ssum[tid + s]; scnt[tid] += scnt[tid + s]; }
        __syncthreads();
    }
    if (tid == 0) {
        int n = scnt[0] > 0 ? scnt[0] : 1;
        out[0] = (float)(ssum[0] / (double)n);
    }
}

extern "C" void kernel_launch(void* const* d_in, const int* in_sizes, int n_in,
                              void* d_out, int out_size) {
    const float* x = (const float*)d_in[0];   // [B*L, C] float32
    const int*   y = (const int*)d_in[1];     // [B*M] int32
    const int B = in_sizes[2];                // num_chars has B entries
    const int blocks = (B + WARPS_PER_BLOCK - 1) / WARPS_PER_BLOCK;
    edit_loss_kernel<<<blocks, WARPS_PER_BLOCK * 32>>>(x, y, B);
    edit_loss_reduce_kernel<<<1, 256>>>((float*)d_out, B);
}

// round 6
// speedup vs baseline: 1.4175x; 1.4175x over previous
#include <cuda_runtime.h>
#include <cuda_bf16.h>

#define B_MAX 8192
#define LCH 32   // predicted chars per sample (L)
#define MLB 32   // labels per sample (M)
#define CCL 96   // classes (C)
#define WARPS_PER_BLOCK 8
#define FULLMASK 0xffffffffu

// Per-sample packed result {mean_ce, flag} (device-global scratch: allowed)
__device__ float2 g_pack[B_MAX];

struct WarpScratch {
    unsigned char D[33 * 34];   // DP table, row stride 34 (1122 B)
    unsigned char pad0[2];
    int   pred[LCH];            // argmax per row (for backtrace)
    int   tgt[MLB];             // labels (for backtrace)
    int2  trace[LCH];           // (row, label) of diagonal steps
    int   cnt;
    int   pad1[3];
};

__device__ __forceinline__ unsigned f2ord(float f) {
    unsigned u = __float_as_uint(f);
    return ((int)u < 0) ? ~u : (u | 0x80000000u);
}
__device__ __forceinline__ float ord2f(unsigned u) {
    return (u & 0x80000000u) ? __uint_as_float(u ^ 0x80000000u)
                             : __uint_as_float(~u);
}

__global__ void __launch_bounds__(WARPS_PER_BLOCK * 32)
edit_loss_kernel(const float* __restrict__ x, const int* __restrict__ y, int B) {
    __shared__ WarpScratch ws[WARPS_PER_BLOCK];
    const int warp = threadIdx.x >> 5;
    const int lane = threadIdx.x & 31;
    const int s = blockIdx.x * WARPS_PER_BLOCK + warp;
    if (s >= B) return;  // warp-uniform

    WarpScratch& W = ws[warp];
    const float* xs = x + (size_t)s * (LCH * CCL);

    const int myTgt = y[s * MLB + lane];
    W.tgt[lane] = myTgt;

    // ---- Phase A: per-row argmax (REDUX) + logsumexp. Lane r retains
    // predReg/baseReg for row r.
    int   predReg = 0;
    float baseReg = 0.f;
    #pragma unroll 4
    for (int r = 0; r < LCH; ++r) {
        const float* row = xs + r * CCL;
        float f0 = row[lane];
        float f1 = row[lane + 32];
        float f2 = row[lane + 64];
        float v = f0; int id = lane;
        if (f1 > v) { v = f1; id = lane + 32; }
        if (f2 > v) { v = f2; id = lane + 64; }
        unsigned ob  = f2ord(v);
        unsigned gm  = __reduce_max_sync(FULLMASK, ob);
        unsigned cnd = (ob == gm) ? (unsigned)id : 0xFFFFFFFFu;
        unsigned gid = __reduce_min_sync(FULLMASK, cnd);   // lowest index on ties
        float vmax = ord2f(gm);
        float sum = __expf(f0 - vmax) + __expf(f1 - vmax) + __expf(f2 - vmax);
        #pragma unroll
        for (int off = 16; off; off >>= 1)
            sum += __shfl_xor_sync(FULLMASK, sum, off);
        if (lane == r) {
            predReg = (int)gid;
            baseReg = vmax + __logf(sum);   // logZ for my row
            W.pred[r] = (int)gid;
        }
    }

    // ---- Per-lane cost column mask: bit r = (pred[r] != tgt[lane])
    unsigned costmask = 0;
    #pragma unroll
    for (int r = 0; r < LCH; ++r) {
        int p = __shfl_sync(FULLMASK, predReg, r);
        costmask |= (unsigned)(p != myTgt) << r;
    }

    // ---- DP boundary rows/cols
    W.D[0 * 34 + lane] = (unsigned char)lane;   // D[0][j] = j
    W.D[lane * 34 + 0] = (unsigned char)lane;   // D[i][0] = i
    if (lane == 0) { W.D[0 * 34 + 32] = 32; W.D[32 * 34 + 0] = 32; }
    __syncwarp();

    // ---- Phase B: Levenshtein wavefront (lane t owns column j = t+1)
    {
        const int t = lane;
        const int j = lane + 1;
        unsigned prev = 0u;     // D[i-1][j]   (my value, previous step)
        unsigned diagv = 0u;    // D[i-1][j-1] (left neighbor, 2 steps ago)
        #pragma unroll 1
        for (int d = 0; d <= LCH + MLB - 2; ++d) {   // 63 anti-diagonals
            unsigned leftIn = __shfl_up_sync(FULLMASK, prev, 1);
            const int i = d - t + 1;
            if (i >= 1 && i <= LCH) {
                unsigned c    = (costmask >> (i - 1)) & 1u;   // register, not LDS
                unsigned up   = (i == 1) ? (unsigned)j : prev;
                unsigned left = (t == 0) ? (unsigned)i : leftIn;
                unsigned dg   = (i == 1) ? (unsigned)(j - 1)
                             : (t == 0) ? (unsigned)(i - 1)
                                        : diagv;
                unsigned val = min(min(up, left) + 1u, dg + c);
                W.D[i * 34 + j] = (unsigned char)val;
                prev = val;
            }
            diagv = leftIn;
        }
    }
    __syncwarp();

    // ---- Phase C: backtrace (serial, lane 0), dij carried in register.
    if (lane == 0) {
        int i = LCH, jj = MLB, cnt = 0;
        int dij = (int)W.D[LCH * 34 + MLB];
        while (i > 0 && jj > 0) {
            const int dd = (int)W.D[(i - 1) * 34 + (jj - 1)];  // independent LDS
            const int du = (int)W.D[(i - 1) * 34 + jj];        // independent LDS
            const int tg = W.tgt[jj - 1];
            const int c  = (W.pred[i - 1] != tg) ? 1 : 0;
            if (dd + c == dij) {
                W.trace[cnt] = make_int2(i - 1, tg);
                ++cnt; --i; --jj; dij = dd;
            } else if (du + 1 == dij) {
                --i; dij = du;
            } else {
                --jj; dij = dij - 1;   // left move always satisfies D[i][j-1]+1==dij
            }
        }
        W.cnt = cnt;
    }
    __syncwarp();

    // ---- Phase D: CE gather + warp reduce
    const int cnt = W.cnt;
    int2 tr = (lane < cnt) ? W.trace[lane] : make_int2(0, 0);
    const float bval = __shfl_sync(FULLMASK, baseReg, tr.x);  // logZ of row tr.x
    float ce = 0.f;
    if (lane < cnt)
        ce = bval - __ldg(&xs[tr.x * CCL + tr.y]);   // -log_softmax at (row,label)
    #pragma unroll
    for (int off = 16; off; off >>= 1)
        ce += __shfl_xor_sync(FULLMASK, ce, off);
    if (lane == 0)
        g_pack[s] = make_float2((cnt > 0) ? (ce / (float)cnt) : 0.f,
                                (cnt > 0) ? 1.f : 0.f);
}

// Deterministic final reduction: float4-vectorized, fixed-order tree.
__global__ void edit_loss_reduce_kernel(float* __restrict__ out, int B) {
    __shared__ float ssum[1024];
    __shared__ float scnt[1024];
    const int tid = threadIdx.x;
    const float4* p = (const float4*)g_pack;   // 2 samples per float4
    const int nv = B >> 1;
    float sum = 0.f, cnt = 0.f;
    for (int i = tid; i < nv; i += 1024) {
        float4 v = p[i];
        sum += v.x + v.z;
        cnt += v.y + v.w;
    }
    if (tid == 0 && (B & 1)) {   // generality guard (B is even here)
        float2 v = g_pack[B - 1];
        sum += v.x; cnt += v.y;
    }
    ssum[tid] = sum; scnt[tid] = cnt;
    __syncthreads();
    #pragma unroll
    for (int st = 512; st; st >>= 1) {
        if (tid < st) { ssum[tid] += ssum[tid + st]; scnt[tid] += scnt[tid + st]; }
        __syncthreads();
    }
    if (tid == 0) {
        float n = scnt[0] > 0.f ? scnt[0] : 1.f;
        out[0] = ssum[0] / n;
    }
}

extern "C" void kernel_launch(void* const* d_in, const int* in_sizes, int n_in,
                              void* d_out, int out_size) {
    const float* x = (const float*)d_in[0];   // [B*L, C] float32
    const int*   y = (const int*)d_in[1];     // [B*M] int32
    const int B = in_sizes[2];                // num_chars has B entries
    const int blocks = (B + WARPS_PER_BLOCK - 1) / WARPS_PER_BLOCK;
    edit_loss_kernel<<<blocks, WARPS_PER_BLOCK * 32>>>(x, y, B);
    edit_loss_reduce_kernel<<<1, 1024>>>((float*)d_out, B);
}

// round 7
// speedup vs baseline: 1.4184x; 1.0006x over previous
#include <cuda_runtime.h>
#include <cuda_bf16.h>

#define B_MAX 8192
#define LCH 32   // predicted chars per sample (L)
#define MLB 32   // labels per sample (M)
#define CCL 96   // classes (C)
#define WARPS_PER_BLOCK 8
#define FULLMASK 0xffffffffu

// Per-sample packed result {mean_ce, flag} (device-global scratch: allowed)
__device__ float2 g_pack[B_MAX];

struct WarpScratch {
    unsigned char D[33 * 34];   // DP table, row stride 34 (1122 B)
    unsigned char pad0[2];
    int   pred[LCH];            // argmax per row (for backtrace)
    int   tgt[MLB];             // labels (for backtrace)
    int2  trace[LCH];           // (row, label) of diagonal steps
    int   cnt;
    int   pad1[3];
};

__device__ __forceinline__ unsigned f2ord(float f) {
    unsigned u = __float_as_uint(f);
    return ((int)u < 0) ? ~u : (u | 0x80000000u);
}
__device__ __forceinline__ float ord2f(unsigned u) {
    return (u & 0x80000000u) ? __uint_as_float(u ^ 0x80000000u)
                             : __uint_as_float(~u);
}

__global__ void __launch_bounds__(WARPS_PER_BLOCK * 32)
edit_loss_kernel(const float* __restrict__ x, const int* __restrict__ y, int B) {
    __shared__ WarpScratch ws[WARPS_PER_BLOCK];
    const int warp = threadIdx.x >> 5;
    const int lane = threadIdx.x & 31;
    const int s = blockIdx.x * WARPS_PER_BLOCK + warp;
    if (s >= B) return;  // warp-uniform

    WarpScratch& W = ws[warp];
    const float* xs = x + (size_t)s * (LCH * CCL);

    const int myTgt = y[s * MLB + lane];
    W.tgt[lane] = myTgt;

    // ---- Phase A: per-row argmax (REDUX) + logsumexp. Lane r retains
    // predReg/baseReg for row r.
    int   predReg = 0;
    float baseReg = 0.f;
    #pragma unroll 4
    for (int r = 0; r < LCH; ++r) {
        const float* row = xs + r * CCL;
        float f0 = row[lane];
        float f1 = row[lane + 32];
        float f2 = row[lane + 64];
        float v = f0; int id = lane;
        if (f1 > v) { v = f1; id = lane + 32; }
        if (f2 > v) { v = f2; id = lane + 64; }
        unsigned ob  = f2ord(v);
        unsigned gm  = __reduce_max_sync(FULLMASK, ob);
        unsigned cnd = (ob == gm) ? (unsigned)id : 0xFFFFFFFFu;
        unsigned gid = __reduce_min_sync(FULLMASK, cnd);   // lowest index on ties
        float vmax = ord2f(gm);
        float sum = __expf(f0 - vmax) + __expf(f1 - vmax) + __expf(f2 - vmax);
        #pragma unroll
        for (int off = 16; off; off >>= 1)
            sum += __shfl_xor_sync(FULLMASK, sum, off);
        if (lane == r) {
            predReg = (int)gid;
            baseReg = vmax + __logf(sum);   // logZ for my row
            W.pred[r] = (int)gid;
        }
    }

    // ---- Per-lane cost column mask: bit r = (pred[r] != tgt[lane])
    unsigned costmask = 0;
    #pragma unroll
    for (int r = 0; r < LCH; ++r) {
        int p = __shfl_sync(FULLMASK, predReg, r);
        costmask |= (unsigned)(p != myTgt) << r;
    }

    // ---- DP boundary rows/cols
    W.D[0 * 34 + lane] = (unsigned char)lane;   // D[0][j] = j
    W.D[lane * 34 + 0] = (unsigned char)lane;   // D[i][0] = i
    if (lane == 0) { W.D[0 * 34 + 32] = 32; W.D[32 * 34 + 0] = 32; }
    __syncwarp();

    // ---- Phase B: Levenshtein wavefront (lane t owns column j = t+1)
    {
        const int t = lane;
        const int j = lane + 1;
        unsigned prev = 0u;     // D[i-1][j]   (my value, previous step)
        unsigned diagv = 0u;    // D[i-1][j-1] (left neighbor, 2 steps ago)
        #pragma unroll 1
        for (int d = 0; d <= LCH + MLB - 2; ++d) {   // 63 anti-diagonals
            unsigned leftIn = __shfl_up_sync(FULLMASK, prev, 1);
            const int i = d - t + 1;
            if (i >= 1 && i <= LCH) {
                unsigned c    = (costmask >> (i - 1)) & 1u;   // register, not LDS
                unsigned up   = (i == 1) ? (unsigned)j : prev;
                unsigned left = (t == 0) ? (unsigned)i : leftIn;
                unsigned dg   = (i == 1) ? (unsigned)(j - 1)
                             : (t == 0) ? (unsigned)(i - 1)
                                        : diagv;
                unsigned val = min(min(up, left) + 1u, dg + c);
                W.D[i * 34 + j] = (unsigned char)val;
                prev = val;
            }
            diagv = leftIn;
        }
    }
    __syncwarp();

    // ---- Phase C: backtrace (serial, lane 0), dij carried in register.
    if (lane == 0) {
        int i = LCH, jj = MLB, cnt = 0;
        int dij = (int)W.D[LCH * 34 + MLB];
        while (i > 0 && jj > 0) {
            const int dd = (int)W.D[(i - 1) * 34 + (jj - 1)];  // independent LDS
            const int du = (int)W.D[(i - 1) * 34 + jj];        // independent LDS
            const int tg = W.tgt[jj - 1];
            const int c  = (W.pred[i - 1] != tg) ? 1 : 0;
            if (dd + c == dij) {
                W.trace[cnt] = make_int2(i - 1, tg);
                ++cnt; --i; --jj; dij = dd;
            } else if (du + 1 == dij) {
                --i; dij = du;
            } else {
                --jj; dij = dij - 1;   // left move always satisfies D[i][j-1]+1==dij
            }
        }
        W.cnt = cnt;
    }
    __syncwarp();

    // ---- Phase D: CE gather + warp reduce
    const int cnt = W.cnt;
    int2 tr = (lane < cnt) ? W.trace[lane] : make_int2(0, 0);
    const float bval = __shfl_sync(FULLMASK, baseReg, tr.x);  // logZ of row tr.x
    float ce = 0.f;
    if (lane < cnt)
        ce = bval - __ldg(&xs[tr.x * CCL + tr.y]);   // -log_softmax at (row,label)
    #pragma unroll
    for (int off = 16; off; off >>= 1)
        ce += __shfl_xor_sync(FULLMASK, ce, off);
    if (lane == 0)
        g_pack[s] = make_float2((cnt > 0) ? (ce / (float)cnt) : 0.f,
                                (cnt > 0) ? 1.f : 0.f);
}

// Deterministic final reduction: float4-vectorized, fixed-order tree.
__global__ void edit_loss_reduce_kernel(float* __restrict__ out, int B) {
    __shared__ float ssum[1024];
    __shared__ float scnt[1024];
    const int tid = threadIdx.x;
    const float4* p = (const float4*)g_pack;   // 2 samples per float4
    const int nv = B >> 1;
    float sum = 0.f, cnt = 0.f;
    for (int i = tid; i < nv; i += 1024) {
        float4 v = p[i];
        sum += v.x + v.z;
        cnt += v.y + v.w;
    }
    if (tid == 0 && (B & 1)) {   // generality guard (B is even here)
        float2 v = g_pack[B - 1];
        sum += v.x; cnt += v.y;
    }
    ssum[tid] = sum; scnt[tid] = cnt;
    __syncthreads();
    #pragma unroll
    for (int st = 512; st; st >>= 1) {
        if (tid < st) { ssum[tid] += ssum[tid + st]; scnt[tid] += scnt[tid + st]; }
        __syncthreads();
    }
    if (tid == 0) {
        float n = scnt[0] > 0.f ? scnt[0] : 1.f;
        out[0] = ssum[0] / n;
    }
}

extern "C" void kernel_launch(void* const* d_in, const int* in_sizes, int n_in,
                              void* d_out, int out_size) {
    const float* x = (const float*)d_in[0];   // [B*L, C] float32
    const int*   y = (const int*)d_in[1];     // [B*M] int32
    const int B = in_sizes[2];                // num_chars has B entries
    const int blocks = (B + WARPS_PER_BLOCK - 1) / WARPS_PER_BLOCK;
    edit_loss_kernel<<<blocks, WARPS_PER_BLOCK * 32>>>(x, y, B);
    edit_loss_reduce_kernel<<<1, 1024>>>((float*)d_out, B);
}